// round 10
// baseline (speedup 1.0000x reference)
#include <cuda_runtime.h>
#include <math.h>

// x: [64, 3, 512, 512] fp32 -> out [192, 6]: per 8x8 block |FFT2| at bins
// (0,1),(1,0),(1,1),(2,2),(3,3),(4,4), mean over 64x64 blocks per plane.
//
// R9: persistent 148-CTA layout, ONE CTA per SM, 1024 threads. Each CTA
// streams one contiguous ~1.3MB region (5-6 plane-aligned 256KB chunks) ->
// exactly 148 concurrent DRAM streams (vs 236+ before) for row-buffer
// locality, 32 warps/SM feeding MLP, single wave. Chunks are plane-aligned
// (1024 tiles each, 4 per plane) so plane is CTA-uniform per step; <=3
// reduction flushes per CTA. Each (plane,band) output cell receives <=2
// atomicAdd contributions (commutative -> bitwise deterministic). Zero
// kernel initializes d_out first.

#define PLANE_ELEMS (512 * 512)
#define TILES_PER_PLANE 4096
#define CHUNK_TILES 1024
#define THREADS 1024
#define GRID 148

__global__ void zero_out_kernel(float* __restrict__ out, int n) {
    int i = blockIdx.x * blockDim.x + threadIdx.x;
    if (i < n) out[i] = 0.0f;
}

__device__ __forceinline__ void flush_plane(float* __restrict__ out, int plane,
                                            const float v_in[6],
                                            float (*red)[6], int tid) {
    float v[6] = {v_in[0], v_in[1], v_in[2], v_in[3], v_in[4], v_in[5]};
    #pragma unroll
    for (int j = 0; j < 6; ++j) {
        #pragma unroll
        for (int o = 16; o > 0; o >>= 1)
            v[j] += __shfl_down_sync(0xffffffffu, v[j], o);
    }
    const int lane = tid & 31, warp = tid >> 5;
    if (lane == 0) {
        #pragma unroll
        for (int j = 0; j < 6; ++j) red[warp][j] = v[j];
    }
    __syncthreads();
    if (tid < 6) {
        float t = 0.f;
        #pragma unroll
        for (int w = 0; w < 32; ++w) t += red[w][tid];
        atomicAdd(&out[plane * 6 + tid], t * (1.0f / (float)TILES_PER_PLANE));
    }
    __syncthreads();   // smem safe for next flush
}

__global__ __launch_bounds__(THREADS, 1)
void dct_bands_kernel(const float* __restrict__ x, float* __restrict__ out,
                      int n_chunks) {
    const int tid = threadIdx.x;
    const int bid = blockIdx.x;
    const int nb  = gridDim.x;
    const int c0 = (int)(((long long)bid * n_chunks) / nb);
    const int c1 = (int)(((long long)(bid + 1) * n_chunks) / nb);

    constexpr float S = 0.70710678118654752440f;
    const float C45[8]  = {1.f,  S, 0.f, -S, -1.f, -S, 0.f,  S};
    const float S45[8]  = {0.f,  S, 1.f,  S,  0.f, -S, -1.f, -S};
    const float C90[8]  = {1.f, 0.f, -1.f, 0.f, 1.f, 0.f, -1.f, 0.f};
    const float S90[8]  = {0.f, 1.f, 0.f, -1.f, 0.f, 1.f, 0.f, -1.f};
    const float C135[8] = {1.f, -S, 0.f,  S, -1.f,  S, 0.f, -S};
    const float S135[8] = {0.f,  S, -1.f, S,  0.f, -S, 1.f, -S};

    __shared__ float red[32][6];

    float s[6] = {0.f, 0.f, 0.f, 0.f, 0.f, 0.f};
    int cur_plane = c0 >> 2;

    #pragma unroll 1
    for (int c = c0; c < c1; ++c) {
        const int plane = c >> 2;                 // chunk -> plane (4 chunks/plane)
        if (plane != cur_plane) {                 // CTA-uniform branch
            flush_plane(out, cur_plane, s, red, tid);
            #pragma unroll
            for (int j = 0; j < 6; ++j) s[j] = 0.f;
            cur_plane = plane;
        }
        const int local = ((c & 3) << 10) | tid;  // tile within plane
        const int gi = local >> 6;                // block row
        const int gj = local & 63;                // block col
        const float* bp = x + (size_t)plane * PLANE_ELEMS
                            + ((size_t)(gi << 3) << 9) + (gj << 3);

        float a01r = 0.f, a01i = 0.f;
        float a10r = 0.f, a10i = 0.f;
        float a11r = 0.f, a11i = 0.f;
        float a22r = 0.f, a22i = 0.f;
        float a33r = 0.f, a33i = 0.f;
        float a44  = 0.f;

        #pragma unroll
        for (int m = 0; m < 8; ++m) {
            const float4 lo = __ldcs(reinterpret_cast<const float4*>(bp + m * 512));
            const float4 hi = __ldcs(reinterpret_cast<const float4*>(bp + m * 512 + 4));
            const float x0 = lo.x, x1 = lo.y, x2 = lo.z, x3 = lo.w;
            const float x4 = hi.x, x5 = hi.y, x6 = hi.z, x7 = hi.w;

            const float p  = x1 - x3 - x5 + x7;
            const float q  = x1 + x3 - x5 - x7;
            const float e0 = x0 - x4;
            const float e2 = x2 - x6;

            const float r0  = x0 + x1 + x2 + x3 + x4 + x5 + x6 + x7;
            const float re1 = e0 + p * S;
            const float im1 = -(q * S + e2);
            const float re2 = x0 - x2 + x4 - x6;
            const float im2 = -(x1 - x3 + x5 - x7);
            const float re3 = e0 - p * S;
            const float im3 = -(q * S - e2);
            const float r4  = x0 - x1 + x2 - x3 + x4 - x5 + x6 - x7;

            const float w1r = C45[m],  w1i = -S45[m];
            const float w2r = C90[m],  w2i = -S90[m];
            const float w3r = C135[m], w3i = -S135[m];

            a01r += re1;                  a01i += im1;
            a10r += r0 * w1r;             a10i += r0 * w1i;
            a11r += re1 * w1r - im1 * w1i;
            a11i += re1 * w1i + im1 * w1r;
            a22r += re2 * w2r - im2 * w2i;
            a22i += re2 * w2i + im2 * w2r;
            a33r += re3 * w3r - im3 * w3i;
            a33i += re3 * w3i + im3 * w3r;
            a44  += (m & 1) ? -r4 : r4;
        }

        s[0] += sqrtf(a01r * a01r + a01i * a01i);
        s[1] += sqrtf(a10r * a10r + a10i * a10i);
        s[2] += sqrtf(a11r * a11r + a11i * a11i);
        s[3] += sqrtf(a22r * a22r + a22i * a22i);
        s[4] += sqrtf(a33r * a33r + a33i * a33i);
        s[5] += fabsf(a44);
    }

    flush_plane(out, cur_plane, s, red, tid);
}

extern "C" void kernel_launch(void* const* d_in, const int* in_sizes, int n_in,
                              void* d_out, int out_size) {
    const float* x = (const float*)d_in[0];
    float* out = (float*)d_out;
    const int n_planes = in_sizes[0] / PLANE_ELEMS;     // 192
    const int n_chunks = n_planes * (TILES_PER_PLANE / CHUNK_TILES);  // 768
    zero_out_kernel<<<(out_size + 255) / 256, 256>>>(out, out_size);
    dct_bands_kernel<<<GRID, THREADS>>>(x, out, n_chunks);
}

// round 11
// speedup vs baseline: 1.2051x; 1.2051x over previous
#include <cuda_runtime.h>
#include <math.h>

// x: [64, 3, 512, 512] fp32 -> out [192, 6]: per 8x8 block |FFT2| at bins
// (0,1),(1,0),(1,1),(2,2),(3,3),(4,4), mean over 64x64 blocks per plane.
//
// R10 = R8 (record: 35.296us wall / 34.62us kernel, 5.92TB/s) + a single
// delta: L2 prefetch of the NEXT tile's 8 rows (128KB ahead, ~4us early),
// issued by lanes 0,4,...,28 (one per 128B line). Goal: smooth the DRAM
// request stream (demand bursts -> steady L2 fill), converting demand LDG
// misses to L2 hits and closing the 25% DRAM-idle gap.

#define PLANE_ELEMS (512 * 512)
#define NBLOCKS_PER_PLANE 4096   // 64 x 64 blocks of 8x8
#define THREADS 512
#define KITERS (NBLOCKS_PER_PLANE / THREADS)   // 8

__global__ __launch_bounds__(THREADS, 2)
void dct_bands_kernel(const float* __restrict__ x, float* __restrict__ out) {
    const int plane = blockIdx.x;                       // b*3 + c, 0..191
    const float* __restrict__ base = x + (size_t)plane * PLANE_ELEMS;
    const int tid  = threadIdx.x;
    const int lane = tid & 31;

    constexpr float S = 0.70710678118654752440f;
    // Twiddle tables: e^{-i * m * theta}; unrolled loop -> folded to immediates.
    const float C45[8]  = {1.f,  S, 0.f, -S, -1.f, -S, 0.f,  S};
    const float S45[8]  = {0.f,  S, 1.f,  S,  0.f, -S, -1.f, -S};
    const float C90[8]  = {1.f, 0.f, -1.f, 0.f, 1.f, 0.f, -1.f, 0.f};
    const float S90[8]  = {0.f, 1.f, 0.f, -1.f, 0.f, 1.f, 0.f, -1.f};
    const float C135[8] = {1.f, -S, 0.f,  S, -1.f,  S, 0.f, -S};
    const float S135[8] = {0.f,  S, -1.f, S,  0.f, -S, 1.f, -S};

    float sum0 = 0.f, sum1 = 0.f, sum2 = 0.f, sum3 = 0.f, sum4 = 0.f, sum5 = 0.f;

    #pragma unroll 1
    for (int k = 0; k < KITERS; ++k) {
        const int bl = tid + (k << 9);            // block index within plane
        const int gi = bl >> 6;                   // block row (0..63)
        const int gj = bl & 63;                   // block col (0..63)
        const float* bp = base + ((size_t)(gi << 3) << 9) + (gj << 3);

        // Prefetch next tile's 8 rows into L2 (thread's k+1 tile sits
        // +8 block-rows = +32768 floats = 128KB ahead). One prefetch per
        // 128B line: lanes 0,4,...,28 cover the warp's 8 lines per row.
        if (k + 1 < KITERS && (lane & 3) == 0) {
            const float* pn = bp + 32768;
            #pragma unroll
            for (int m = 0; m < 8; ++m)
                asm volatile("prefetch.global.L2 [%0];" :: "l"(pn + m * 512));
        }

        float a01r = 0.f, a01i = 0.f;
        float a10r = 0.f, a10i = 0.f;
        float a11r = 0.f, a11i = 0.f;
        float a22r = 0.f, a22i = 0.f;
        float a33r = 0.f, a33i = 0.f;
        float a44  = 0.f;

        #pragma unroll
        for (int m = 0; m < 8; ++m) {
            const float4 lo = __ldcs(reinterpret_cast<const float4*>(bp + m * 512));
            const float4 hi = __ldcs(reinterpret_cast<const float4*>(bp + m * 512 + 4));
            const float x0 = lo.x, x1 = lo.y, x2 = lo.z, x3 = lo.w;
            const float x4 = hi.x, x5 = hi.y, x6 = hi.z, x7 = hi.w;

            const float p  = x1 - x3 - x5 + x7;
            const float q  = x1 + x3 - x5 - x7;
            const float e0 = x0 - x4;
            const float e2 = x2 - x6;

            const float r0  = x0 + x1 + x2 + x3 + x4 + x5 + x6 + x7;
            const float re1 = e0 + p * S;
            const float im1 = -(q * S + e2);
            const float re2 = x0 - x2 + x4 - x6;
            const float im2 = -(x1 - x3 + x5 - x7);
            const float re3 = e0 - p * S;
            const float im3 = -(q * S - e2);
            const float r4  = x0 - x1 + x2 - x3 + x4 - x5 + x6 - x7;

            const float w1r = C45[m],  w1i = -S45[m];
            const float w2r = C90[m],  w2i = -S90[m];
            const float w3r = C135[m], w3i = -S135[m];

            a01r += re1;                  a01i += im1;
            a10r += r0 * w1r;             a10i += r0 * w1i;
            a11r += re1 * w1r - im1 * w1i;
            a11i += re1 * w1i + im1 * w1r;
            a22r += re2 * w2r - im2 * w2i;
            a22i += re2 * w2i + im2 * w2r;
            a33r += re3 * w3r - im3 * w3i;
            a33i += re3 * w3i + im3 * w3r;
            a44  += (m & 1) ? -r4 : r4;
        }

        sum0 += sqrtf(a01r * a01r + a01i * a01i);
        sum1 += sqrtf(a10r * a10r + a10i * a10i);
        sum2 += sqrtf(a11r * a11r + a11i * a11i);
        sum3 += sqrtf(a22r * a22r + a22i * a22i);
        sum4 += sqrtf(a33r * a33r + a33i * a33i);
        sum5 += fabsf(a44);
    }

    // ---- CTA reduction: 512 threads x 6 floats -> out[plane*6 + band] ----
    float v[6] = {sum0, sum1, sum2, sum3, sum4, sum5};

    #pragma unroll
    for (int j = 0; j < 6; ++j) {
        #pragma unroll
        for (int o = 16; o > 0; o >>= 1)
            v[j] += __shfl_down_sync(0xffffffffu, v[j], o);
    }

    __shared__ float red[16][6];
    const int warp = tid >> 5;
    if (lane == 0) {
        #pragma unroll
        for (int j = 0; j < 6; ++j) red[warp][j] = v[j];
    }
    __syncthreads();

    if (tid < 6) {
        float t = 0.f;
        #pragma unroll
        for (int w = 0; w < 16; ++w) t += red[w][tid];
        out[plane * 6 + tid] = t * (1.0f / (float)NBLOCKS_PER_PLANE);
    }
}

extern "C" void kernel_launch(void* const* d_in, const int* in_sizes, int n_in,
                              void* d_out, int out_size) {
    const float* x = (const float*)d_in[0];
    float* out = (float*)d_out;
    const int n_planes = in_sizes[0] / PLANE_ELEMS;   // 64*3 = 192
    dct_bands_kernel<<<n_planes, THREADS>>>(x, out);
}